// round 11
// baseline (speedup 1.0000x reference)
#include <cuda_runtime.h>
#include <cuda_bf16.h>

#define N_LOW   20000
#define N_HIGH  150000
#define SEQ     25
#define ENC     32
#define DD      16
#define E_L2H   1350000
#define E_HH    1200000
#define EPSF    1e-5f
#define SLOPE   0.2f
#define SCAN_B  1024
#define NB_SCAN ((N_HIGH + SCAN_B - 1) / SCAN_B)

// ---------------- static device scratch ----------------
__device__ float4 g_WihP[525];             // GRU Wih padded K=28, [75 gates][7 float4]
__device__ float4 g_WhhP[525];
__device__ float  g_WtF[20000];            // dense_W transposed [625 feat][32 enc]
__device__ float  g_xT[625 * N_LOW];       // x_low transposed [feat][node]
__device__ float  g_hT[625 * N_LOW];       // GRU outputs transposed [feat(t*25+j)][node]
__device__ float  g_enc[N_LOW * ENC];      // relu(dense) raw (pre-BN)
__device__ float  g_x[N_HIGH * DD];        // current node features (raw, pre-BN)
__device__ float  g_xl[N_HIGH * DD];
__device__ float  g_xr[N_HIGH * DD];
__device__ int    g_countsA[N_HIGH];
__device__ int    g_countsB[N_HIGH];
__device__ int    g_rpA[N_HIGH + 1];
__device__ int    g_curA[N_HIGH];
__device__ int    g_colA[E_L2H];
__device__ int    g_rpB[N_HIGH + 1];
__device__ int    g_curB[N_HIGH];
__device__ int    g_colB[E_HH];
__device__ int    g_bsumA[256];
__device__ int    g_bsumB[256];
__device__ float  g_stats[64];             // [0:32) sum, [32:64) sumsq
__device__ float  g_sc32[32], g_sh32[32];  // folded BN for enc
__device__ float  g_sc16[16], g_sh16[16];  // folded BN for 16-d stages

// ---------------- prep (+init): pad GRU weights, transpose dense_W, zero counters ----------------
__global__ void k_prep(const float* __restrict__ Wih, const float* __restrict__ Whh,
                       const float* __restrict__ dW) {
    int i = blockIdx.x * blockDim.x + threadIdx.x;
    if (i < 525) {
        int g = i / 7, q = i % 7;
        float4 a, b;
        float* pa = (float*)&a; float* pb = (float*)&b;
        #pragma unroll
        for (int c = 0; c < 4; c++) {
            int k = q * 4 + c;
            pa[c] = (k < 25) ? Wih[g * 25 + k] : 0.f;
            pb[c] = (k < 25) ? Whh[g * 25 + k] : 0.f;
        }
        g_WihP[i] = a; g_WhhP[i] = b;
    } else if (i < 525 + 20000) {
        int j = i - 525;
        int f = j >> 5, e = j & 31;
        g_WtF[j] = dW[e * 625 + f];
    }
    if (i < N_HIGH) { g_countsA[i] = 0; g_countsB[i] = 0; }
    if (i < 64) g_stats[i] = 0.f;
}

__global__ void k_transx(const float* __restrict__ x) {  // [20000,625] -> [625,20000]
    __shared__ float tile[32][33];
    int f = blockIdx.x * 32 + threadIdx.x;
    int n = blockIdx.y * 32 + threadIdx.y;
    if (f < 625 && n < N_LOW) tile[threadIdx.y][threadIdx.x] = x[n * 625 + f];
    __syncthreads();
    int f2 = blockIdx.x * 32 + threadIdx.y;
    int n2 = blockIdx.y * 32 + threadIdx.x;
    if (f2 < 625 && n2 < N_LOW) g_xT[f2 * N_LOW + n2] = tile[threadIdx.x][threadIdx.y];
}

// ---------------- GRU (thread-per-node; known-good 396us config) ----------------
__device__ __forceinline__ float sigm(float x) { return __fdividef(1.f, 1.f + __expf(-x)); }

__global__ __launch_bounds__(128) void k_gru(const float* __restrict__ bih,
                                             const float* __restrict__ bhh) {
    __shared__ float4 sWih[525], sWhh[525];
    __shared__ float sbih[75], sbhh[75];
    for (int i = threadIdx.x; i < 525; i += 128) { sWih[i] = g_WihP[i]; sWhh[i] = g_WhhP[i]; }
    for (int i = threadIdx.x; i < 75;  i += 128) { sbih[i] = bih[i]; sbhh[i] = bhh[i]; }
    __syncthreads();
    int n = blockIdx.x * 128 + threadIdx.x;
    if (n >= N_LOW) return;

    float h[28], xt[28], hn[25];
    #pragma unroll
    for (int k = 0; k < 28; k++) { h[k] = 0.f; xt[k] = 0.f; }

    #pragma unroll 1
    for (int t = 0; t < SEQ; t++) {
        #pragma unroll
        for (int k = 0; k < 25; k++) xt[k] = g_xT[(t * 25 + k) * N_LOW + n];
        #pragma unroll
        for (int j = 0; j < 25; j++) {
            float sr = sbih[j] + sbhh[j];
            float sz = sbih[25 + j] + sbhh[25 + j];
            float si = sbih[50 + j];
            float sh = sbhh[50 + j];
            #pragma unroll
            for (int q = 0; q < 7; q++) {
                float4 wir = sWih[j * 7 + q];
                float4 whr = sWhh[j * 7 + q];
                float4 wiz = sWih[(25 + j) * 7 + q];
                float4 whz = sWhh[(25 + j) * 7 + q];
                float4 win = sWih[(50 + j) * 7 + q];
                float4 whn = sWhh[(50 + j) * 7 + q];
                float x0 = xt[4*q], x1 = xt[4*q+1], x2 = xt[4*q+2], x3 = xt[4*q+3];
                float h0 = h[4*q],  h1 = h[4*q+1],  h2 = h[4*q+2],  h3 = h[4*q+3];
                sr += x0*wir.x + x1*wir.y + x2*wir.z + x3*wir.w;
                sr += h0*whr.x + h1*whr.y + h2*whr.z + h3*whr.w;
                sz += x0*wiz.x + x1*wiz.y + x2*wiz.z + x3*wiz.w;
                sz += h0*whz.x + h1*whz.y + h2*whz.z + h3*whz.w;
                si += x0*win.x + x1*win.y + x2*win.z + x3*win.w;
                sh += h0*whn.x + h1*whn.y + h2*whn.z + h3*whn.w;
            }
            float r = sigm(sr);
            float z = sigm(sz);
            float nn = tanhf(si + r * sh);
            hn[j] = nn + z * (h[j] - nn);
        }
        #pragma unroll
        for (int j = 0; j < 25; j++) {
            h[j] = hn[j];
            g_hT[(t * 25 + j) * N_LOW + n] = hn[j];   // coalesced across n
        }
    }
}

// ---------------- dense 625->32: 4 threads/node, 8 enc outputs each ----------------
__global__ __launch_bounds__(256) void k_dense4(const float* __restrict__ db) {
    __shared__ float sW[125 * 32];          // 16 KB chunk of Wt
    __shared__ float sdb[32];
    __shared__ float sS[8][32], sQ[8][32];  // per-warp per-feature partials
    int tid = threadIdx.x;
    if (tid < 32) sdb[tid] = db[tid];
    int gt   = blockIdx.x * 256 + tid;
    int node = gt >> 2;
    int sub  = gt & 3;                      // enc base = sub*8
    bool act = (node < N_LOW);
    int lane = tid & 31, wrp = tid >> 5;

    float enc[8];
    #pragma unroll
    for (int k = 0; k < 8; k++) enc[k] = 0.f;

    #pragma unroll 1
    for (int c = 0; c < 5; c++) {
        __syncthreads();
        for (int i = tid; i < 125 * 32; i += 256) sW[i] = g_WtF[c * 125 * 32 + i];
        __syncthreads();
        if (act) {
            #pragma unroll 1
            for (int f = 0; f < 125; f++) {
                float v = g_hT[(c * 125 + f) * N_LOW + node];
                float4 w0 = ((const float4*)(sW + f * 32 + sub * 8))[0];
                float4 w1 = ((const float4*)(sW + f * 32 + sub * 8))[1];
                enc[0] += v * w0.x; enc[1] += v * w0.y;
                enc[2] += v * w0.z; enc[3] += v * w0.w;
                enc[4] += v * w1.x; enc[5] += v * w1.y;
                enc[6] += v * w1.z; enc[7] += v * w1.w;
            }
        }
    }
    // bias + relu + store (coalesced: thread writes 8 consecutive floats at gt*8)
    float vr[8];
    #pragma unroll
    for (int k = 0; k < 8; k++) {
        vr[k] = act ? fmaxf(enc[k] + sdb[sub * 8 + k], 0.f) : 0.f;
    }
    if (act) {
        float4* dst = (float4*)(g_enc + (size_t)gt * 8);
        dst[0] = make_float4(vr[0], vr[1], vr[2], vr[3]);
        dst[1] = make_float4(vr[4], vr[5], vr[6], vr[7]);
    }
    // BN stats: lanes with equal (lane&3) hold the same 8 features
    #pragma unroll
    for (int k = 0; k < 8; k++) {
        float s = vr[k], q = vr[k] * vr[k];
        #pragma unroll
        for (int off = 4; off < 32; off <<= 1) {
            s += __shfl_xor_sync(0xffffffffu, s, off);
            q += __shfl_xor_sync(0xffffffffu, q, off);
        }
        if (lane < 4) { sS[wrp][lane * 8 + k] = s; sQ[wrp][lane * 8 + k] = q; }
    }
    __syncthreads();
    if (tid < 32) {
        float ts = 0.f, tq = 0.f;
        #pragma unroll
        for (int w = 0; w < 8; w++) { ts += sS[w][tid]; tq += sQ[w][tid]; }
        atomicAdd(&g_stats[tid], ts);
        atomicAdd(&g_stats[32 + tid], tq);
    }
}

// ---------------- BN finalize (1 block; race-free: read -> barrier -> zero) ----------------
__global__ void k_finalize(const float* __restrict__ g, const float* __restrict__ b,
                           int nf, float invN, int target) {
    int f = threadIdx.x;
    float sum = 0.f, sq = 0.f;
    if (f < nf) { sum = g_stats[f]; sq = g_stats[32 + f]; }
    __syncthreads();
    if (f < 64) g_stats[f] = 0.f;
    if (f < nf) {
        float m  = sum * invN;
        float v  = fmaxf(sq * invN - m * m, 0.f);
        float sc = g[f] * rsqrtf(v + EPSF);
        float sh = b[f] - m * sc;
        if (target == 0) { g_sc32[f] = sc; g_sh32[f] = sh; }
        else             { g_sc16[f] = sc; g_sh16[f] = sh; }
    }
}

// ---------------- merged CSR build for both graphs ----------------
__global__ void k_histAB(const int* __restrict__ dA, const int* __restrict__ dB) {
    int stride = gridDim.x * blockDim.x;
    for (int e = blockIdx.x * blockDim.x + threadIdx.x; e < E_L2H + E_HH; e += stride) {
        if (e < E_L2H) atomicAdd(&g_countsA[dA[e]], 1);
        else           atomicAdd(&g_countsB[dB[e - E_L2H]], 1);
    }
}

__global__ void k_scan1() {
    const int* counts = blockIdx.y ? g_countsB : g_countsA;
    int* bsum = blockIdx.y ? g_bsumB : g_bsumA;
    __shared__ int sh[SCAN_B];
    int i = blockIdx.x * SCAN_B + threadIdx.x;
    sh[threadIdx.x] = (i < N_HIGH) ? counts[i] : 0;
    __syncthreads();
    for (int off = SCAN_B / 2; off > 0; off >>= 1) {
        if (threadIdx.x < off) sh[threadIdx.x] += sh[threadIdx.x + off];
        __syncthreads();
    }
    if (threadIdx.x == 0) bsum[blockIdx.x] = sh[0];
}

__global__ void k_scan2() {
    int* bsum = blockIdx.x ? g_bsumB : g_bsumA;
    __shared__ int sh[256];
    int t = threadIdx.x;
    int c = (t < NB_SCAN) ? bsum[t] : 0;
    sh[t] = c;
    __syncthreads();
    for (int off = 1; off < 256; off <<= 1) {
        int v = (t >= off) ? sh[t - off] : 0;
        __syncthreads();
        sh[t] += v;
        __syncthreads();
    }
    if (t < NB_SCAN) bsum[t] = sh[t] - c;
}

__global__ void k_scan3() {
    int which = blockIdx.y;
    const int* counts = which ? g_countsB : g_countsA;
    const int* bsum   = which ? g_bsumB   : g_bsumA;
    int* rp  = which ? g_rpB  : g_rpA;
    int* cur = which ? g_curB : g_curA;
    __shared__ int sh[SCAN_B];
    int i = blockIdx.x * SCAN_B + threadIdx.x;
    int c = (i < N_HIGH) ? counts[i] : 0;
    sh[threadIdx.x] = c;
    __syncthreads();
    for (int off = 1; off < SCAN_B; off <<= 1) {
        int v = (threadIdx.x >= off) ? sh[threadIdx.x - off] : 0;
        __syncthreads();
        sh[threadIdx.x] += v;
        __syncthreads();
    }
    int incl = sh[threadIdx.x];
    int base = bsum[blockIdx.x];
    if (i < N_HIGH) {
        int excl = base + incl - c;
        rp[i] = excl; cur[i] = excl;
        if (i == N_HIGH - 1) rp[N_HIGH] = base + incl;
    }
}

__global__ void k_fillAB(const int* __restrict__ sA, const int* __restrict__ dA,
                         const int* __restrict__ sB, const int* __restrict__ dB) {
    int stride = gridDim.x * blockDim.x;
    for (int e = blockIdx.x * blockDim.x + threadIdx.x; e < E_L2H + E_HH; e += stride) {
        if (e < E_L2H) {
            int p = atomicAdd(&g_curA[dA[e]], 1);
            g_colA[p] = sA[e];
        } else {
            int i = e - E_L2H;
            int p = atomicAdd(&g_curB[dB[i]], 1);
            g_colB[p] = sB[i];
        }
    }
}

// ---------------- fused: l2h mean aggregation + BN + down-projection + BN0 stats ----------------
__global__ __launch_bounds__(256) void k_aggdown(const float* __restrict__ z,
                                                 const float* __restrict__ land,
                                                 const float* __restrict__ Wrel,
                                                 const float* __restrict__ brel,
                                                 const float* __restrict__ Wroot) {
    __shared__ float sAgg[8 * 32];
    __shared__ float sWrel[512];
    __shared__ float sX[128], sQ[128];
    int tid = threadIdx.x;
    sWrel[tid] = Wrel[tid];
    sWrel[tid + 256] = Wrel[tid + 256];

    int node8 = tid >> 5, lane = tid & 31;
    int node = blockIdx.x * 8 + node8;
    int beg = g_rpA[node], end = g_rpA[node + 1];
    float acc = 0.f;
    for (int p = beg; p < end; p++) {
        int s = g_colA[p];
        acc += g_enc[s * 32 + lane];
    }
    int deg = end - beg;
    float val = 0.f;
    if (deg > 0) val = (acc / (float)deg) * g_sc32[lane] + g_sh32[lane];
    sAgg[node8 * 32 + lane] = val;
    __syncthreads();

    if (tid < 128) {
        int n8 = tid >> 4, d = tid & 15;
        int gn = blockIdx.x * 8 + n8;
        float a = brel[d];
        #pragma unroll
        for (int k = 0; k < 32; k++) a = fmaf(sAgg[n8 * 32 + k], sWrel[d * 32 + k], a);
        #pragma unroll
        for (int k = 0; k < 6; k++) a = fmaf(z[gn * 6 + k], Wroot[d * 7 + k], a);
        a = fmaf(land[gn], Wroot[d * 7 + 6], a);
        g_x[gn * 16 + d] = a;
        sX[tid] = a; sQ[tid] = a * a;
    }
    __syncthreads();
    #pragma unroll
    for (int off = 4; off > 0; off >>= 1) {
        if (tid < off * 16) { sX[tid] += sX[tid + off * 16]; sQ[tid] += sQ[tid + off * 16]; }
        __syncthreads();
    }
    if (tid < 16) {
        atomicAdd(&g_stats[tid], sX[tid]);
        atomicAdd(&g_stats[32 + tid], sQ[tid]);
    }
}

// ---------------- per-layer transform: BN (+ReLU) folded, compute xl, xr ----------------
__global__ __launch_bounds__(256) void k_transform(const float* __restrict__ Wl,
                                                   const float* __restrict__ bl,
                                                   const float* __restrict__ Wr,
                                                   const float* __restrict__ br,
                                                   int do_relu) {
    __shared__ float sWl[256], sWr[256], sbl[16], sbr[16], ssc[16], ssh[16];
    int tid = threadIdx.x;
    sWl[tid] = Wl[tid]; sWr[tid] = Wr[tid];
    if (tid < 16) { sbl[tid] = bl[tid]; sbr[tid] = br[tid]; ssc[tid] = g_sc16[tid]; ssh[tid] = g_sh16[tid]; }
    __syncthreads();
    int t = blockIdx.x * 256 + tid;
    int node = t >> 4, d = t & 15;
    float xb = g_x[node * 16 + d] * ssc[d] + ssh[d];
    if (do_relu) xb = fmaxf(xb, 0.f);
    float al = sbl[d], ar = sbr[d];
    #pragma unroll
    for (int k = 0; k < 16; k++) {
        float v = __shfl_sync(0xffffffffu, xb, k, 16);
        al = fmaf(sWl[d * 16 + k], v, al);
        ar = fmaf(sWr[d * 16 + k], v, ar);
    }
    g_xl[node * 16 + d] = al;
    g_xr[node * 16 + d] = ar;
}

// ---------------- GATv2: unroll-2 edge loop, plain exp, fused stats / pred ----------------
__global__ __launch_bounds__(256) void k_gat(const float* __restrict__ att,
                                             const float* __restrict__ bias,
                                             int mode,                    // 0: +BN stats, 1: +pred
                                             const float* __restrict__ pW,
                                             const float* __restrict__ pb,
                                             float* __restrict__ out) {
    int tid = threadIdx.x;
    int t = blockIdx.x * 256 + tid;
    int node = t >> 4, d = t & 15;
    float att_d  = att[d];
    float bias_d = bias[d];
    float xr_d   = g_xr[node * 16 + d];
    int beg = g_rpB[node], end = g_rpB[node + 1];
    int deg = end - beg;
    int otherDeg = __shfl_xor_sync(0xffffffffu, deg, 16);
    int degMax = max(deg, otherDeg);                    // warp-uniform loop bound

    // self loop first
    float xls0 = g_xl[node * 16 + d];
    float u0 = xls0 + xr_d;
    u0 = fmaxf(u0, 0.f) + SLOPE * fminf(u0, 0.f);
    float tv0 = u0 * att_d;
    tv0 += __shfl_xor_sync(0xffffffffu, tv0, 8, 16);
    tv0 += __shfl_xor_sync(0xffffffffu, tv0, 4, 16);
    tv0 += __shfl_xor_sync(0xffffffffu, tv0, 2, 16);
    tv0 += __shfl_xor_sync(0xffffffffu, tv0, 1, 16);
    float w0 = __expf(tv0);
    float s = w0, acc = w0 * xls0;

    for (int i = 0; i < degMax; i += 2) {               // two independent shuffle chains
        int p1 = beg + i, p2 = beg + i + 1;
        bool v1 = (p1 < end), v2 = (p2 < end);
        int s1 = v1 ? g_colB[p1] : node;
        int s2 = v2 ? g_colB[p2] : node;
        float a = g_xl[s1 * 16 + d];
        float b = g_xl[s2 * 16 + d];
        float u1 = a + xr_d; u1 = fmaxf(u1, 0.f) + SLOPE * fminf(u1, 0.f);
        float u2 = b + xr_d; u2 = fmaxf(u2, 0.f) + SLOPE * fminf(u2, 0.f);
        float t1 = u1 * att_d, t2 = u2 * att_d;
        t1 += __shfl_xor_sync(0xffffffffu, t1, 8, 16);
        t2 += __shfl_xor_sync(0xffffffffu, t2, 8, 16);
        t1 += __shfl_xor_sync(0xffffffffu, t1, 4, 16);
        t2 += __shfl_xor_sync(0xffffffffu, t2, 4, 16);
        t1 += __shfl_xor_sync(0xffffffffu, t1, 2, 16);
        t2 += __shfl_xor_sync(0xffffffffu, t2, 2, 16);
        t1 += __shfl_xor_sync(0xffffffffu, t1, 1, 16);
        t2 += __shfl_xor_sync(0xffffffffu, t2, 1, 16);
        if (v1) { float w = __expf(t1); s += w; acc = fmaf(w, a, acc); }
        if (v2) { float w = __expf(t2); s += w; acc = fmaf(w, b, acc); }
    }
    float cnt = (float)(deg + 1);
    float val = __fdividef(acc, s * cnt) + bias_d;

    if (mode == 1) {
        float r = fmaxf(val, 0.f) * pW[d];
        r += __shfl_xor_sync(0xffffffffu, r, 8, 16);
        r += __shfl_xor_sync(0xffffffffu, r, 4, 16);
        r += __shfl_xor_sync(0xffffffffu, r, 2, 16);
        r += __shfl_xor_sync(0xffffffffu, r, 1, 16);
        if (d == 0) out[node] = r + pb[0];
        return;
    }
    g_x[node * 16 + d] = val;

    __shared__ float sX[256], sQ[256];
    sX[tid] = val; sQ[tid] = val * val;
    __syncthreads();
    #pragma unroll
    for (int off = 8; off > 0; off >>= 1) {
        if (tid < off * 16) { sX[tid] += sX[tid + off * 16]; sQ[tid] += sQ[tid + off * 16]; }
        __syncthreads();
    }
    if (tid < 16) {
        atomicAdd(&g_stats[tid], sX[tid]);
        atomicAdd(&g_stats[32 + tid], sQ[tid]);
    }
}

// ---------------- launch ----------------
extern "C" void kernel_launch(void* const* d_in, const int* in_sizes, int n_in,
                              void* d_out, int out_size) {
    const float* x_low   = (const float*)d_in[0];
    const float* z_std   = (const float*)d_in[1];
    const float* land    = (const float*)d_in[2];
    const int*   l2h_src = (const int*)d_in[3];
    const int*   l2h_dst = (const int*)d_in[4];
    const int*   hh_src  = (const int*)d_in[5];
    const int*   hh_dst  = (const int*)d_in[6];
    const float* gWih    = (const float*)d_in[7];
    const float* gWhh    = (const float*)d_in[8];
    const float* gbih    = (const float*)d_in[9];
    const float* gbhh    = (const float*)d_in[10];
    const float* dW      = (const float*)d_in[11];
    const float* db      = (const float*)d_in[12];
    const float* bnencg  = (const float*)d_in[13];
    const float* bnencb  = (const float*)d_in[14];
    const float* Wrel    = (const float*)d_in[15];
    const float* brel    = (const float*)d_in[16];
    const float* Wroot   = (const float*)d_in[17];
    const float* gWl     = (const float*)d_in[18];
    const float* gbl     = (const float*)d_in[19];
    const float* gWr     = (const float*)d_in[20];
    const float* gbr     = (const float*)d_in[21];
    const float* gatt    = (const float*)d_in[22];
    const float* gbias   = (const float*)d_in[23];
    const float* bn_g    = (const float*)d_in[24];
    const float* bn_b    = (const float*)d_in[25];
    const float* pW      = (const float*)d_in[26];
    const float* pb      = (const float*)d_in[27];
    float* out = (float*)d_out;

    k_prep<<<(N_HIGH + 255) / 256, 256>>>(gWih, gWhh, dW);             // 1 (init merged)
    k_transx<<<dim3(20, 625), dim3(32, 32)>>>(x_low);                  // 2
    k_gru<<<157, 128>>>(gbih, gbhh);                                   // 3
    k_dense4<<<313, 256>>>(db);                                        // 4  <- profiled
    k_finalize<<<1, 64>>>(bnencg, bnencb, 32, 1.f / N_LOW, 0);         // 5
    k_histAB<<<1024, 256>>>(l2h_dst, hh_dst);                          // 6
    k_scan1<<<dim3(NB_SCAN, 2), SCAN_B>>>();                           // 7
    k_scan2<<<2, 256>>>();                                             // 8
    k_scan3<<<dim3(NB_SCAN, 2), SCAN_B>>>();                           // 9
    k_fillAB<<<1024, 256>>>(l2h_src, l2h_dst, hh_src, hh_dst);         // 10
    k_aggdown<<<18750, 256>>>(z_std, land, Wrel, brel, Wroot);         // 11
    k_finalize<<<1, 64>>>(bn_g, bn_b, 16, 1.f / N_HIGH, 1);            // 12

    for (int i = 0; i < 5; i++) {
        k_transform<<<9375, 256>>>(gWl + i * 256, gbl + i * 16,
                                   gWr + i * 256, gbr + i * 16, i > 0 ? 1 : 0);
        if (i < 4) {
            k_gat<<<9375, 256>>>(gatt + i * 16, gbias + i * 16, 0, nullptr, nullptr, nullptr);
            k_finalize<<<1, 64>>>(bn_g + (i + 1) * 16, bn_b + (i + 1) * 16, 16, 1.f / N_HIGH, 1);
        } else {
            k_gat<<<9375, 256>>>(gatt + i * 16, gbias + i * 16, 1, pW, pb, out);
        }
    }
}

// round 12
// speedup vs baseline: 1.1427x; 1.1427x over previous
#include <cuda_runtime.h>
#include <cuda_bf16.h>

#define N_LOW   20000
#define N_HIGH  150000
#define SEQ     25
#define ENC     32
#define DD      16
#define E_L2H   1350000
#define E_HH    1200000
#define EPSF    1e-5f
#define SLOPE   0.2f
#define SCAN_B  1024
#define NB_SCAN ((N_HIGH + SCAN_B - 1) / SCAN_B)

// ---------------- static device scratch ----------------
__device__ float4 g_WihP[525];             // GRU Wih padded K=28, [75 gates][7 float4]
__device__ float4 g_WhhP[525];
__device__ float  g_WtF[20000];            // dense_W transposed [625 feat][32 enc]
__device__ float  g_xT[625 * N_LOW];       // x_low transposed [feat][node]
__device__ float  g_hT[625 * N_LOW];       // GRU outputs transposed [feat(t*25+j)][node]
__device__ float  g_enc[N_LOW * ENC];      // relu(dense) raw (pre-BN)
__device__ float  g_x[N_HIGH * DD];        // current node features (raw, pre-BN)
__device__ float  g_xl[N_HIGH * DD];
__device__ float  g_xr[N_HIGH * DD];
__device__ int    g_countsA[N_HIGH];
__device__ int    g_countsB[N_HIGH];
__device__ int    g_rpA[N_HIGH + 1];
__device__ int    g_curA[N_HIGH];
__device__ int    g_colA[E_L2H];
__device__ int    g_rpB[N_HIGH + 1];
__device__ int    g_curB[N_HIGH];
__device__ int    g_colB[E_HH];
__device__ int    g_bsumA[256];
__device__ int    g_bsumB[256];
__device__ float  g_stats[64];             // [0:32) sum, [32:64) sumsq
__device__ float  g_sc32[32], g_sh32[32];  // folded BN for enc
__device__ float  g_sc16[16], g_sh16[16];  // folded BN for 16-d stages

// ---------------- prep (+init): pad GRU weights, transpose dense_W, zero counters ----------------
__global__ void k_prep(const float* __restrict__ Wih, const float* __restrict__ Whh,
                       const float* __restrict__ dW) {
    int i = blockIdx.x * blockDim.x + threadIdx.x;
    if (i < 525) {
        int g = i / 7, q = i % 7;
        float4 a, b;
        float* pa = (float*)&a; float* pb = (float*)&b;
        #pragma unroll
        for (int c = 0; c < 4; c++) {
            int k = q * 4 + c;
            pa[c] = (k < 25) ? Wih[g * 25 + k] : 0.f;
            pb[c] = (k < 25) ? Whh[g * 25 + k] : 0.f;
        }
        g_WihP[i] = a; g_WhhP[i] = b;
    } else if (i < 525 + 20000) {
        int j = i - 525;
        int f = j >> 5, e = j & 31;
        g_WtF[j] = dW[e * 625 + f];
    }
    if (i < N_HIGH) { g_countsA[i] = 0; g_countsB[i] = 0; }
    if (i < 64) g_stats[i] = 0.f;
}

__global__ void k_transx(const float* __restrict__ x) {  // [20000,625] -> [625,20000]
    __shared__ float tile[32][33];
    int f = blockIdx.x * 32 + threadIdx.x;
    int n = blockIdx.y * 32 + threadIdx.y;
    if (f < 625 && n < N_LOW) tile[threadIdx.y][threadIdx.x] = x[n * 625 + f];
    __syncthreads();
    int f2 = blockIdx.x * 32 + threadIdx.y;
    int n2 = blockIdx.y * 32 + threadIdx.x;
    if (f2 < 625 && n2 < N_LOW) g_xT[f2 * N_LOW + n2] = tile[threadIdx.x][threadIdx.y];
}

// ---------------- GRU (thread-per-node; known-good 396us config) ----------------
__device__ __forceinline__ float sigm(float x) { return __fdividef(1.f, 1.f + __expf(-x)); }

__global__ __launch_bounds__(128) void k_gru(const float* __restrict__ bih,
                                             const float* __restrict__ bhh) {
    __shared__ float4 sWih[525], sWhh[525];
    __shared__ float sbih[75], sbhh[75];
    for (int i = threadIdx.x; i < 525; i += 128) { sWih[i] = g_WihP[i]; sWhh[i] = g_WhhP[i]; }
    for (int i = threadIdx.x; i < 75;  i += 128) { sbih[i] = bih[i]; sbhh[i] = bhh[i]; }
    __syncthreads();
    int n = blockIdx.x * 128 + threadIdx.x;
    if (n >= N_LOW) return;

    float h[28], xt[28], hn[25];
    #pragma unroll
    for (int k = 0; k < 28; k++) { h[k] = 0.f; xt[k] = 0.f; }

    #pragma unroll 1
    for (int t = 0; t < SEQ; t++) {
        #pragma unroll
        for (int k = 0; k < 25; k++) xt[k] = g_xT[(t * 25 + k) * N_LOW + n];
        #pragma unroll
        for (int j = 0; j < 25; j++) {
            float sr = sbih[j] + sbhh[j];
            float sz = sbih[25 + j] + sbhh[25 + j];
            float si = sbih[50 + j];
            float sh = sbhh[50 + j];
            #pragma unroll
            for (int q = 0; q < 7; q++) {
                float4 wir = sWih[j * 7 + q];
                float4 whr = sWhh[j * 7 + q];
                float4 wiz = sWih[(25 + j) * 7 + q];
                float4 whz = sWhh[(25 + j) * 7 + q];
                float4 win = sWih[(50 + j) * 7 + q];
                float4 whn = sWhh[(50 + j) * 7 + q];
                float x0 = xt[4*q], x1 = xt[4*q+1], x2 = xt[4*q+2], x3 = xt[4*q+3];
                float h0 = h[4*q],  h1 = h[4*q+1],  h2 = h[4*q+2],  h3 = h[4*q+3];
                sr += x0*wir.x + x1*wir.y + x2*wir.z + x3*wir.w;
                sr += h0*whr.x + h1*whr.y + h2*whr.z + h3*whr.w;
                sz += x0*wiz.x + x1*wiz.y + x2*wiz.z + x3*wiz.w;
                sz += h0*whz.x + h1*whz.y + h2*whz.z + h3*whz.w;
                si += x0*win.x + x1*win.y + x2*win.z + x3*win.w;
                sh += h0*whn.x + h1*whn.y + h2*whn.z + h3*whn.w;
            }
            float r = sigm(sr);
            float z = sigm(sz);
            float nn = tanhf(si + r * sh);
            hn[j] = nn + z * (h[j] - nn);
        }
        #pragma unroll
        for (int j = 0; j < 25; j++) {
            h[j] = hn[j];
            g_hT[(t * 25 + j) * N_LOW + n] = hn[j];   // coalesced across n
        }
    }
}

// ---------------- dense 625->32: 4 threads/node, 8 outputs each, MLP-25 loads ----------------
__global__ __launch_bounds__(256) void k_dense4(const float* __restrict__ db) {
    __shared__ float sW[125 * 32];          // 16 KB chunk of Wt
    __shared__ float sdb[32];
    __shared__ float sS[8][32], sQ[8][32];  // per-warp per-feature partials
    int tid = threadIdx.x;
    if (tid < 32) sdb[tid] = db[tid];
    int gt   = blockIdx.x * 256 + tid;
    int node = gt >> 2;
    int sub  = gt & 3;                      // enc base = sub*8
    bool act = (node < N_LOW);
    int lane = tid & 31, wrp = tid >> 5;

    float enc[8];
    #pragma unroll
    for (int k = 0; k < 8; k++) enc[k] = 0.f;

    #pragma unroll 1
    for (int c = 0; c < 5; c++) {
        __syncthreads();
        for (int i = tid; i < 125 * 32; i += 256) sW[i] = g_WtF[c * 125 * 32 + i];
        __syncthreads();
        if (act) {
            #pragma unroll 1
            for (int f0 = 0; f0 < 125; f0 += 25) {
                // batch 25 independent LDGs -> MLP=25, latency amortized
                float v[25];
                #pragma unroll
                for (int u = 0; u < 25; u++)
                    v[u] = g_hT[(c * 125 + f0 + u) * N_LOW + node];
                #pragma unroll
                for (int u = 0; u < 25; u++) {
                    const float4* wp = (const float4*)(sW + (f0 + u) * 32 + sub * 8);
                    float4 w0 = wp[0], w1 = wp[1];
                    float vu = v[u];
                    enc[0] += vu * w0.x; enc[1] += vu * w0.y;
                    enc[2] += vu * w0.z; enc[3] += vu * w0.w;
                    enc[4] += vu * w1.x; enc[5] += vu * w1.y;
                    enc[6] += vu * w1.z; enc[7] += vu * w1.w;
                }
            }
        }
    }
    // bias + relu + store (coalesced: thread writes 8 consecutive floats at gt*8)
    float vr[8];
    #pragma unroll
    for (int k = 0; k < 8; k++) {
        vr[k] = act ? fmaxf(enc[k] + sdb[sub * 8 + k], 0.f) : 0.f;
    }
    if (act) {
        float4* dst = (float4*)(g_enc + (size_t)gt * 8);
        dst[0] = make_float4(vr[0], vr[1], vr[2], vr[3]);
        dst[1] = make_float4(vr[4], vr[5], vr[6], vr[7]);
    }
    // BN stats: lanes with equal (lane&3) hold the same 8 features
    #pragma unroll
    for (int k = 0; k < 8; k++) {
        float s = vr[k], q = vr[k] * vr[k];
        #pragma unroll
        for (int off = 4; off < 32; off <<= 1) {
            s += __shfl_xor_sync(0xffffffffu, s, off);
            q += __shfl_xor_sync(0xffffffffu, q, off);
        }
        if (lane < 4) { sS[wrp][lane * 8 + k] = s; sQ[wrp][lane * 8 + k] = q; }
    }
    __syncthreads();
    if (tid < 32) {
        float ts = 0.f, tq = 0.f;
        #pragma unroll
        for (int w = 0; w < 8; w++) { ts += sS[w][tid]; tq += sQ[w][tid]; }
        atomicAdd(&g_stats[tid], ts);
        atomicAdd(&g_stats[32 + tid], tq);
    }
}

// ---------------- BN finalize (1 block; race-free: read -> barrier -> zero) ----------------
__global__ void k_finalize(const float* __restrict__ g, const float* __restrict__ b,
                           int nf, float invN, int target) {
    int f = threadIdx.x;
    float sum = 0.f, sq = 0.f;
    if (f < nf) { sum = g_stats[f]; sq = g_stats[32 + f]; }
    __syncthreads();
    if (f < 64) g_stats[f] = 0.f;
    if (f < nf) {
        float m  = sum * invN;
        float v  = fmaxf(sq * invN - m * m, 0.f);
        float sc = g[f] * rsqrtf(v + EPSF);
        float sh = b[f] - m * sc;
        if (target == 0) { g_sc32[f] = sc; g_sh32[f] = sh; }
        else             { g_sc16[f] = sc; g_sh16[f] = sh; }
    }
}

// ---------------- merged CSR build for both graphs ----------------
__global__ void k_histAB(const int* __restrict__ dA, const int* __restrict__ dB) {
    int stride = gridDim.x * blockDim.x;
    for (int e = blockIdx.x * blockDim.x + threadIdx.x; e < E_L2H + E_HH; e += stride) {
        if (e < E_L2H) atomicAdd(&g_countsA[dA[e]], 1);
        else           atomicAdd(&g_countsB[dB[e - E_L2H]], 1);
    }
}

__global__ void k_scan1() {
    const int* counts = blockIdx.y ? g_countsB : g_countsA;
    int* bsum = blockIdx.y ? g_bsumB : g_bsumA;
    __shared__ int sh[SCAN_B];
    int i = blockIdx.x * SCAN_B + threadIdx.x;
    sh[threadIdx.x] = (i < N_HIGH) ? counts[i] : 0;
    __syncthreads();
    for (int off = SCAN_B / 2; off > 0; off >>= 1) {
        if (threadIdx.x < off) sh[threadIdx.x] += sh[threadIdx.x + off];
        __syncthreads();
    }
    if (threadIdx.x == 0) bsum[blockIdx.x] = sh[0];
}

__global__ void k_scan2() {
    int* bsum = blockIdx.x ? g_bsumB : g_bsumA;
    __shared__ int sh[256];
    int t = threadIdx.x;
    int c = (t < NB_SCAN) ? bsum[t] : 0;
    sh[t] = c;
    __syncthreads();
    for (int off = 1; off < 256; off <<= 1) {
        int v = (t >= off) ? sh[t - off] : 0;
        __syncthreads();
        sh[t] += v;
        __syncthreads();
    }
    if (t < NB_SCAN) bsum[t] = sh[t] - c;
}

__global__ void k_scan3() {
    int which = blockIdx.y;
    const int* counts = which ? g_countsB : g_countsA;
    const int* bsum   = which ? g_bsumB   : g_bsumA;
    int* rp  = which ? g_rpB  : g_rpA;
    int* cur = which ? g_curB : g_curA;
    __shared__ int sh[SCAN_B];
    int i = blockIdx.x * SCAN_B + threadIdx.x;
    int c = (i < N_HIGH) ? counts[i] : 0;
    sh[threadIdx.x] = c;
    __syncthreads();
    for (int off = 1; off < SCAN_B; off <<= 1) {
        int v = (threadIdx.x >= off) ? sh[threadIdx.x - off] : 0;
        __syncthreads();
        sh[threadIdx.x] += v;
        __syncthreads();
    }
    int incl = sh[threadIdx.x];
    int base = bsum[blockIdx.x];
    if (i < N_HIGH) {
        int excl = base + incl - c;
        rp[i] = excl; cur[i] = excl;
        if (i == N_HIGH - 1) rp[N_HIGH] = base + incl;
    }
}

__global__ void k_fillAB(const int* __restrict__ sA, const int* __restrict__ dA,
                         const int* __restrict__ sB, const int* __restrict__ dB) {
    int stride = gridDim.x * blockDim.x;
    for (int e = blockIdx.x * blockDim.x + threadIdx.x; e < E_L2H + E_HH; e += stride) {
        if (e < E_L2H) {
            int p = atomicAdd(&g_curA[dA[e]], 1);
            g_colA[p] = sA[e];
        } else {
            int i = e - E_L2H;
            int p = atomicAdd(&g_curB[dB[i]], 1);
            g_colB[p] = sB[i];
        }
    }
}

// ---------------- fused: l2h mean aggregation + BN + down-projection + BN0 stats ----------------
__global__ __launch_bounds__(256) void k_aggdown(const float* __restrict__ z,
                                                 const float* __restrict__ land,
                                                 const float* __restrict__ Wrel,
                                                 const float* __restrict__ brel,
                                                 const float* __restrict__ Wroot) {
    __shared__ float sAgg[8 * 32];
    __shared__ float sWrel[512];
    __shared__ float sX[128], sQ[128];
    int tid = threadIdx.x;
    sWrel[tid] = Wrel[tid];
    sWrel[tid + 256] = Wrel[tid + 256];

    int node8 = tid >> 5, lane = tid & 31;
    int node = blockIdx.x * 8 + node8;
    int beg = g_rpA[node], end = g_rpA[node + 1];
    float acc = 0.f;
    for (int p = beg; p < end; p++) {
        int s = g_colA[p];
        acc += g_enc[s * 32 + lane];
    }
    int deg = end - beg;
    float val = 0.f;
    if (deg > 0) val = (acc / (float)deg) * g_sc32[lane] + g_sh32[lane];
    sAgg[node8 * 32 + lane] = val;
    __syncthreads();

    if (tid < 128) {
        int n8 = tid >> 4, d = tid & 15;
        int gn = blockIdx.x * 8 + n8;
        float a = brel[d];
        #pragma unroll
        for (int k = 0; k < 32; k++) a = fmaf(sAgg[n8 * 32 + k], sWrel[d * 32 + k], a);
        #pragma unroll
        for (int k = 0; k < 6; k++) a = fmaf(z[gn * 6 + k], Wroot[d * 7 + k], a);
        a = fmaf(land[gn], Wroot[d * 7 + 6], a);
        g_x[gn * 16 + d] = a;
        sX[tid] = a; sQ[tid] = a * a;
    }
    __syncthreads();
    #pragma unroll
    for (int off = 4; off > 0; off >>= 1) {
        if (tid < off * 16) { sX[tid] += sX[tid + off * 16]; sQ[tid] += sQ[tid + off * 16]; }
        __syncthreads();
    }
    if (tid < 16) {
        atomicAdd(&g_stats[tid], sX[tid]);
        atomicAdd(&g_stats[32 + tid], sQ[tid]);
    }
}

// ---------------- per-layer transform: BN (+ReLU) folded, compute xl, xr ----------------
__global__ __launch_bounds__(256) void k_transform(const float* __restrict__ Wl,
                                                   const float* __restrict__ bl,
                                                   const float* __restrict__ Wr,
                                                   const float* __restrict__ br,
                                                   int do_relu) {
    __shared__ float sWl[256], sWr[256], sbl[16], sbr[16], ssc[16], ssh[16];
    int tid = threadIdx.x;
    sWl[tid] = Wl[tid]; sWr[tid] = Wr[tid];
    if (tid < 16) { sbl[tid] = bl[tid]; sbr[tid] = br[tid]; ssc[tid] = g_sc16[tid]; ssh[tid] = g_sh16[tid]; }
    __syncthreads();
    int t = blockIdx.x * 256 + tid;
    int node = t >> 4, d = t & 15;
    float xb = g_x[node * 16 + d] * ssc[d] + ssh[d];
    if (do_relu) xb = fmaxf(xb, 0.f);
    float al = sbl[d], ar = sbr[d];
    #pragma unroll
    for (int k = 0; k < 16; k++) {
        float v = __shfl_sync(0xffffffffu, xb, k, 16);
        al = fmaf(sWl[d * 16 + k], v, al);
        ar = fmaf(sWr[d * 16 + k], v, ar);
    }
    g_xl[node * 16 + d] = al;
    g_xr[node * 16 + d] = ar;
}

// ---------------- GATv2: unroll-2 edge loop, plain exp, fused stats / pred ----------------
__global__ __launch_bounds__(256) void k_gat(const float* __restrict__ att,
                                             const float* __restrict__ bias,
                                             int mode,                    // 0: +BN stats, 1: +pred
                                             const float* __restrict__ pW,
                                             const float* __restrict__ pb,
                                             float* __restrict__ out) {
    int tid = threadIdx.x;
    int t = blockIdx.x * 256 + tid;
    int node = t >> 4, d = t & 15;
    float att_d  = att[d];
    float bias_d = bias[d];
    float xr_d   = g_xr[node * 16 + d];
    int beg = g_rpB[node], end = g_rpB[node + 1];
    int deg = end - beg;
    int otherDeg = __shfl_xor_sync(0xffffffffu, deg, 16);
    int degMax = max(deg, otherDeg);                    // warp-uniform loop bound

    // self loop first
    float xls0 = g_xl[node * 16 + d];
    float u0 = xls0 + xr_d;
    u0 = fmaxf(u0, 0.f) + SLOPE * fminf(u0, 0.f);
    float tv0 = u0 * att_d;
    tv0 += __shfl_xor_sync(0xffffffffu, tv0, 8, 16);
    tv0 += __shfl_xor_sync(0xffffffffu, tv0, 4, 16);
    tv0 += __shfl_xor_sync(0xffffffffu, tv0, 2, 16);
    tv0 += __shfl_xor_sync(0xffffffffu, tv0, 1, 16);
    float w0 = __expf(tv0);
    float s = w0, acc = w0 * xls0;

    for (int i = 0; i < degMax; i += 2) {               // two independent shuffle chains
        int p1 = beg + i, p2 = beg + i + 1;
        bool v1 = (p1 < end), v2 = (p2 < end);
        int s1 = v1 ? g_colB[p1] : node;
        int s2 = v2 ? g_colB[p2] : node;
        float a = g_xl[s1 * 16 + d];
        float b = g_xl[s2 * 16 + d];
        float u1 = a + xr_d; u1 = fmaxf(u1, 0.f) + SLOPE * fminf(u1, 0.f);
        float u2 = b + xr_d; u2 = fmaxf(u2, 0.f) + SLOPE * fminf(u2, 0.f);
        float t1 = u1 * att_d, t2 = u2 * att_d;
        t1 += __shfl_xor_sync(0xffffffffu, t1, 8, 16);
        t2 += __shfl_xor_sync(0xffffffffu, t2, 8, 16);
        t1 += __shfl_xor_sync(0xffffffffu, t1, 4, 16);
        t2 += __shfl_xor_sync(0xffffffffu, t2, 4, 16);
        t1 += __shfl_xor_sync(0xffffffffu, t1, 2, 16);
        t2 += __shfl_xor_sync(0xffffffffu, t2, 2, 16);
        t1 += __shfl_xor_sync(0xffffffffu, t1, 1, 16);
        t2 += __shfl_xor_sync(0xffffffffu, t2, 1, 16);
        if (v1) { float w = __expf(t1); s += w; acc = fmaf(w, a, acc); }
        if (v2) { float w = __expf(t2); s += w; acc = fmaf(w, b, acc); }
    }
    float cnt = (float)(deg + 1);
    float val = __fdividef(acc, s * cnt) + bias_d;

    if (mode == 1) {
        float r = fmaxf(val, 0.f) * pW[d];
        r += __shfl_xor_sync(0xffffffffu, r, 8, 16);
        r += __shfl_xor_sync(0xffffffffu, r, 4, 16);
        r += __shfl_xor_sync(0xffffffffu, r, 2, 16);
        r += __shfl_xor_sync(0xffffffffu, r, 1, 16);
        if (d == 0) out[node] = r + pb[0];
        return;
    }
    g_x[node * 16 + d] = val;

    __shared__ float sX[256], sQ[256];
    sX[tid] = val; sQ[tid] = val * val;
    __syncthreads();
    #pragma unroll
    for (int off = 8; off > 0; off >>= 1) {
        if (tid < off * 16) { sX[tid] += sX[tid + off * 16]; sQ[tid] += sQ[tid + off * 16]; }
        __syncthreads();
    }
    if (tid < 16) {
        atomicAdd(&g_stats[tid], sX[tid]);
        atomicAdd(&g_stats[32 + tid], sQ[tid]);
    }
}

// ---------------- launch ----------------
extern "C" void kernel_launch(void* const* d_in, const int* in_sizes, int n_in,
                              void* d_out, int out_size) {
    const float* x_low   = (const float*)d_in[0];
    const float* z_std   = (const float*)d_in[1];
    const float* land    = (const float*)d_in[2];
    const int*   l2h_src = (const int*)d_in[3];
    const int*   l2h_dst = (const int*)d_in[4];
    const int*   hh_src  = (const int*)d_in[5];
    const int*   hh_dst  = (const int*)d_in[6];
    const float* gWih    = (const float*)d_in[7];
    const float* gWhh    = (const float*)d_in[8];
    const float* gbih    = (const float*)d_in[9];
    const float* gbhh    = (const float*)d_in[10];
    const float* dW      = (const float*)d_in[11];
    const float* db      = (const float*)d_in[12];
    const float* bnencg  = (const float*)d_in[13];
    const float* bnencb  = (const float*)d_in[14];
    const float* Wrel    = (const float*)d_in[15];
    const float* brel    = (const float*)d_in[16];
    const float* Wroot   = (const float*)d_in[17];
    const float* gWl     = (const float*)d_in[18];
    const float* gbl     = (const float*)d_in[19];
    const float* gWr     = (const float*)d_in[20];
    const float* gbr     = (const float*)d_in[21];
    const float* gatt    = (const float*)d_in[22];
    const float* gbias   = (const float*)d_in[23];
    const float* bn_g    = (const float*)d_in[24];
    const float* bn_b    = (const float*)d_in[25];
    const float* pW      = (const float*)d_in[26];
    const float* pb      = (const float*)d_in[27];
    float* out = (float*)d_out;

    k_prep<<<(N_HIGH + 255) / 256, 256>>>(gWih, gWhh, dW);             // 1 (init merged)
    k_transx<<<dim3(20, 625), dim3(32, 32)>>>(x_low);                  // 2
    k_gru<<<157, 128>>>(gbih, gbhh);                                   // 3
    k_dense4<<<313, 256>>>(db);                                        // 4  <- profiled
    k_finalize<<<1, 64>>>(bnencg, bnencb, 32, 1.f / N_LOW, 0);         // 5
    k_histAB<<<1024, 256>>>(l2h_dst, hh_dst);                          // 6
    k_scan1<<<dim3(NB_SCAN, 2), SCAN_B>>>();                           // 7
    k_scan2<<<2, 256>>>();                                             // 8
    k_scan3<<<dim3(NB_SCAN, 2), SCAN_B>>>();                           // 9
    k_fillAB<<<1024, 256>>>(l2h_src, l2h_dst, hh_src, hh_dst);         // 10
    k_aggdown<<<18750, 256>>>(z_std, land, Wrel, brel, Wroot);         // 11
    k_finalize<<<1, 64>>>(bn_g, bn_b, 16, 1.f / N_HIGH, 1);            // 12

    for (int i = 0; i < 5; i++) {
        k_transform<<<9375, 256>>>(gWl + i * 256, gbl + i * 16,
                                   gWr + i * 256, gbr + i * 16, i > 0 ? 1 : 0);
        if (i < 4) {
            k_gat<<<9375, 256>>>(gatt + i * 16, gbias + i * 16, 0, nullptr, nullptr, nullptr);
            k_finalize<<<1, 64>>>(bn_g + (i + 1) * 16, bn_b + (i + 1) * 16, 16, 1.f / N_HIGH, 1);
        } else {
            k_gat<<<9375, 256>>>(gatt + i * 16, gbias + i * 16, 1, pW, pb, out);
        }
    }
}

// round 13
// speedup vs baseline: 1.1746x; 1.0279x over previous
#include <cuda_runtime.h>
#include <cuda_bf16.h>

#define N_LOW   20000
#define N_HIGH  150000
#define SEQ     25
#define ENC     32
#define DD      16
#define E_L2H   1350000
#define E_HH    1200000
#define EPSF    1e-5f
#define SLOPE   0.2f
#define SCAN_B  1024
#define NB_SCAN ((N_HIGH + SCAN_B - 1) / SCAN_B)

// ---------------- static device scratch ----------------
__device__ float4 g_WihP[525];             // GRU Wih padded K=28, [75 gates][7 float4]
__device__ float4 g_WhhP[525];
__device__ float  g_WtF[20000];            // dense_W transposed [625 feat][32 enc]
__device__ float  g_xT[625 * N_LOW];       // x_low transposed [feat][node]
__device__ float  g_hT[625 * N_LOW];       // GRU outputs transposed [feat(t*25+j)][node]
__device__ float  g_enc[N_LOW * ENC];      // relu(dense) raw (pre-BN)
__device__ float  g_x[N_HIGH * DD];        // current node features (raw, pre-BN)
__device__ float  g_xl[N_HIGH * DD];
__device__ float  g_xr[N_HIGH * DD];
__device__ int    g_countsA[N_HIGH];
__device__ int    g_countsB[N_HIGH];
__device__ int    g_rpA[N_HIGH + 1];
__device__ int    g_curA[N_HIGH];
__device__ int    g_colA[E_L2H];
__device__ int    g_rpB[N_HIGH + 1];
__device__ int    g_curB[N_HIGH];
__device__ int    g_colB[E_HH];
__device__ int    g_bsumA[256];
__device__ int    g_bsumB[256];
__device__ float  g_stats[64];             // [0:32) sum, [32:64) sumsq
__device__ float  g_sc32[32], g_sh32[32];  // folded BN for enc
__device__ float  g_sc16[16], g_sh16[16];  // folded BN for 16-d stages

// ---------------- prep (+init): pad GRU weights, transpose dense_W, zero counters ----------------
__global__ void k_prep(const float* __restrict__ Wih, const float* __restrict__ Whh,
                       const float* __restrict__ dW) {
    int i = blockIdx.x * blockDim.x + threadIdx.x;
    if (i < 525) {
        int g = i / 7, q = i % 7;
        float4 a, b;
        float* pa = (float*)&a; float* pb = (float*)&b;
        #pragma unroll
        for (int c = 0; c < 4; c++) {
            int k = q * 4 + c;
            pa[c] = (k < 25) ? Wih[g * 25 + k] : 0.f;
            pb[c] = (k < 25) ? Whh[g * 25 + k] : 0.f;
        }
        g_WihP[i] = a; g_WhhP[i] = b;
    } else if (i < 525 + 20000) {
        int j = i - 525;
        int f = j >> 5, e = j & 31;
        g_WtF[j] = dW[e * 625 + f];
    }
    if (i < N_HIGH) { g_countsA[i] = 0; g_countsB[i] = 0; }
    if (i < 64) g_stats[i] = 0.f;
}

__global__ void k_transx(const float* __restrict__ x) {  // [20000,625] -> [625,20000]
    __shared__ float tile[32][33];
    int f = blockIdx.x * 32 + threadIdx.x;
    int n = blockIdx.y * 32 + threadIdx.y;
    if (f < 625 && n < N_LOW) tile[threadIdx.y][threadIdx.x] = x[n * 625 + f];
    __syncthreads();
    int f2 = blockIdx.x * 32 + threadIdx.y;
    int n2 = blockIdx.y * 32 + threadIdx.x;
    if (f2 < 625 && n2 < N_LOW) g_xT[f2 * N_LOW + n2] = tile[threadIdx.x][threadIdx.y];
}

// ---------------- GRU (thread-per-node; known-good 396us config) ----------------
__device__ __forceinline__ float sigm(float x) { return __fdividef(1.f, 1.f + __expf(-x)); }

__global__ __launch_bounds__(128) void k_gru(const float* __restrict__ bih,
                                             const float* __restrict__ bhh) {
    __shared__ float4 sWih[525], sWhh[525];
    __shared__ float sbih[75], sbhh[75];
    for (int i = threadIdx.x; i < 525; i += 128) { sWih[i] = g_WihP[i]; sWhh[i] = g_WhhP[i]; }
    for (int i = threadIdx.x; i < 75;  i += 128) { sbih[i] = bih[i]; sbhh[i] = bhh[i]; }
    __syncthreads();
    int n = blockIdx.x * 128 + threadIdx.x;
    if (n >= N_LOW) return;

    float h[28], xt[28], hn[25];
    #pragma unroll
    for (int k = 0; k < 28; k++) { h[k] = 0.f; xt[k] = 0.f; }

    #pragma unroll 1
    for (int t = 0; t < SEQ; t++) {
        #pragma unroll
        for (int k = 0; k < 25; k++) xt[k] = g_xT[(t * 25 + k) * N_LOW + n];
        #pragma unroll
        for (int j = 0; j < 25; j++) {
            float sr = sbih[j] + sbhh[j];
            float sz = sbih[25 + j] + sbhh[25 + j];
            float si = sbih[50 + j];
            float sh = sbhh[50 + j];
            #pragma unroll
            for (int q = 0; q < 7; q++) {
                float4 wir = sWih[j * 7 + q];
                float4 whr = sWhh[j * 7 + q];
                float4 wiz = sWih[(25 + j) * 7 + q];
                float4 whz = sWhh[(25 + j) * 7 + q];
                float4 win = sWih[(50 + j) * 7 + q];
                float4 whn = sWhh[(50 + j) * 7 + q];
                float x0 = xt[4*q], x1 = xt[4*q+1], x2 = xt[4*q+2], x3 = xt[4*q+3];
                float h0 = h[4*q],  h1 = h[4*q+1],  h2 = h[4*q+2],  h3 = h[4*q+3];
                sr += x0*wir.x + x1*wir.y + x2*wir.z + x3*wir.w;
                sr += h0*whr.x + h1*whr.y + h2*whr.z + h3*whr.w;
                sz += x0*wiz.x + x1*wiz.y + x2*wiz.z + x3*wiz.w;
                sz += h0*whz.x + h1*whz.y + h2*whz.z + h3*whz.w;
                si += x0*win.x + x1*win.y + x2*win.z + x3*win.w;
                sh += h0*whn.x + h1*whn.y + h2*whn.z + h3*whn.w;
            }
            float r = sigm(sr);
            float z = sigm(sz);
            float nn = tanhf(si + r * sh);
            hn[j] = nn + z * (h[j] - nn);
        }
        #pragma unroll
        for (int j = 0; j < 25; j++) {
            h[j] = hn[j];
            g_hT[(t * 25 + j) * N_LOW + n] = hn[j];   // coalesced across n
        }
    }
}

// ---------------- dense 625->32: 4 threads/node, 8 outputs each, MLP-25 loads ----------------
__global__ __launch_bounds__(256) void k_dense4(const float* __restrict__ db) {
    __shared__ float sW[125 * 32];          // 16 KB chunk of Wt
    __shared__ float sdb[32];
    __shared__ float sS[8][32], sQ[8][32];  // per-warp per-feature partials
    int tid = threadIdx.x;
    if (tid < 32) sdb[tid] = db[tid];
    int gt   = blockIdx.x * 256 + tid;
    int node = gt >> 2;
    int sub  = gt & 3;                      // enc base = sub*8
    bool act = (node < N_LOW);
    int lane = tid & 31, wrp = tid >> 5;

    float enc[8];
    #pragma unroll
    for (int k = 0; k < 8; k++) enc[k] = 0.f;

    #pragma unroll 1
    for (int c = 0; c < 5; c++) {
        __syncthreads();
        for (int i = tid; i < 125 * 32; i += 256) sW[i] = g_WtF[c * 125 * 32 + i];
        __syncthreads();
        if (act) {
            #pragma unroll 1
            for (int f0 = 0; f0 < 125; f0 += 25) {
                float v[25];
                #pragma unroll
                for (int u = 0; u < 25; u++)
                    v[u] = g_hT[(c * 125 + f0 + u) * N_LOW + node];
                #pragma unroll
                for (int u = 0; u < 25; u++) {
                    const float4* wp = (const float4*)(sW + (f0 + u) * 32 + sub * 8);
                    float4 w0 = wp[0], w1 = wp[1];
                    float vu = v[u];
                    enc[0] += vu * w0.x; enc[1] += vu * w0.y;
                    enc[2] += vu * w0.z; enc[3] += vu * w0.w;
                    enc[4] += vu * w1.x; enc[5] += vu * w1.y;
                    enc[6] += vu * w1.z; enc[7] += vu * w1.w;
                }
            }
        }
    }
    float vr[8];
    #pragma unroll
    for (int k = 0; k < 8; k++) {
        vr[k] = act ? fmaxf(enc[k] + sdb[sub * 8 + k], 0.f) : 0.f;
    }
    if (act) {
        float4* dst = (float4*)(g_enc + (size_t)gt * 8);
        dst[0] = make_float4(vr[0], vr[1], vr[2], vr[3]);
        dst[1] = make_float4(vr[4], vr[5], vr[6], vr[7]);
    }
    #pragma unroll
    for (int k = 0; k < 8; k++) {
        float s = vr[k], q = vr[k] * vr[k];
        #pragma unroll
        for (int off = 4; off < 32; off <<= 1) {
            s += __shfl_xor_sync(0xffffffffu, s, off);
            q += __shfl_xor_sync(0xffffffffu, q, off);
        }
        if (lane < 4) { sS[wrp][lane * 8 + k] = s; sQ[wrp][lane * 8 + k] = q; }
    }
    __syncthreads();
    if (tid < 32) {
        float ts = 0.f, tq = 0.f;
        #pragma unroll
        for (int w = 0; w < 8; w++) { ts += sS[w][tid]; tq += sQ[w][tid]; }
        atomicAdd(&g_stats[tid], ts);
        atomicAdd(&g_stats[32 + tid], tq);
    }
}

// ---------------- BN finalize (1 block; race-free: read -> barrier -> zero) ----------------
__global__ void k_finalize(const float* __restrict__ g, const float* __restrict__ b,
                           int nf, float invN, int target) {
    int f = threadIdx.x;
    float sum = 0.f, sq = 0.f;
    if (f < nf) { sum = g_stats[f]; sq = g_stats[32 + f]; }
    __syncthreads();
    if (f < 64) g_stats[f] = 0.f;
    if (f < nf) {
        float m  = sum * invN;
        float v  = fmaxf(sq * invN - m * m, 0.f);
        float sc = g[f] * rsqrtf(v + EPSF);
        float sh = b[f] - m * sc;
        if (target == 0) { g_sc32[f] = sc; g_sh32[f] = sh; }
        else             { g_sc16[f] = sc; g_sh16[f] = sh; }
    }
}

// ---------------- merged CSR build for both graphs ----------------
__global__ void k_histAB(const int* __restrict__ dA, const int* __restrict__ dB) {
    int stride = gridDim.x * blockDim.x;
    for (int e = blockIdx.x * blockDim.x + threadIdx.x; e < E_L2H + E_HH; e += stride) {
        if (e < E_L2H) atomicAdd(&g_countsA[dA[e]], 1);
        else           atomicAdd(&g_countsB[dB[e - E_L2H]], 1);
    }
}

__global__ void k_scan1() {
    const int* counts = blockIdx.y ? g_countsB : g_countsA;
    int* bsum = blockIdx.y ? g_bsumB : g_bsumA;
    __shared__ int sh[SCAN_B];
    int i = blockIdx.x * SCAN_B + threadIdx.x;
    sh[threadIdx.x] = (i < N_HIGH) ? counts[i] : 0;
    __syncthreads();
    for (int off = SCAN_B / 2; off > 0; off >>= 1) {
        if (threadIdx.x < off) sh[threadIdx.x] += sh[threadIdx.x + off];
        __syncthreads();
    }
    if (threadIdx.x == 0) bsum[blockIdx.x] = sh[0];
}

__global__ void k_scan2() {
    int* bsum = blockIdx.x ? g_bsumB : g_bsumA;
    __shared__ int sh[256];
    int t = threadIdx.x;
    int c = (t < NB_SCAN) ? bsum[t] : 0;
    sh[t] = c;
    __syncthreads();
    for (int off = 1; off < 256; off <<= 1) {
        int v = (t >= off) ? sh[t - off] : 0;
        __syncthreads();
        sh[t] += v;
        __syncthreads();
    }
    if (t < NB_SCAN) bsum[t] = sh[t] - c;
}

__global__ void k_scan3() {
    int which = blockIdx.y;
    const int* counts = which ? g_countsB : g_countsA;
    const int* bsum   = which ? g_bsumB   : g_bsumA;
    int* rp  = which ? g_rpB  : g_rpA;
    int* cur = which ? g_curB : g_curA;
    __shared__ int sh[SCAN_B];
    int i = blockIdx.x * SCAN_B + threadIdx.x;
    int c = (i < N_HIGH) ? counts[i] : 0;
    sh[threadIdx.x] = c;
    __syncthreads();
    for (int off = 1; off < SCAN_B; off <<= 1) {
        int v = (threadIdx.x >= off) ? sh[threadIdx.x - off] : 0;
        __syncthreads();
        sh[threadIdx.x] += v;
        __syncthreads();
    }
    int incl = sh[threadIdx.x];
    int base = bsum[blockIdx.x];
    if (i < N_HIGH) {
        int excl = base + incl - c;
        rp[i] = excl; cur[i] = excl;
        if (i == N_HIGH - 1) rp[N_HIGH] = base + incl;
    }
}

__global__ void k_fillAB(const int* __restrict__ sA, const int* __restrict__ dA,
                         const int* __restrict__ sB, const int* __restrict__ dB) {
    int stride = gridDim.x * blockDim.x;
    for (int e = blockIdx.x * blockDim.x + threadIdx.x; e < E_L2H + E_HH; e += stride) {
        if (e < E_L2H) {
            int p = atomicAdd(&g_curA[dA[e]], 1);
            g_colA[p] = sA[e];
        } else {
            int i = e - E_L2H;
            int p = atomicAdd(&g_curB[dB[i]], 1);
            g_colB[p] = sB[i];
        }
    }
}

// ---------------- fused: l2h mean aggregation + BN + down-projection + BN0 stats ----------------
__global__ __launch_bounds__(256) void k_aggdown(const float* __restrict__ z,
                                                 const float* __restrict__ land,
                                                 const float* __restrict__ Wrel,
                                                 const float* __restrict__ brel,
                                                 const float* __restrict__ Wroot) {
    __shared__ float sAgg[8 * 32];
    __shared__ float sWrel[512];
    __shared__ float sX[128], sQ[128];
    int tid = threadIdx.x;
    sWrel[tid] = Wrel[tid];
    sWrel[tid + 256] = Wrel[tid + 256];

    int node8 = tid >> 5, lane = tid & 31;
    int node = blockIdx.x * 8 + node8;
    int beg = g_rpA[node], end = g_rpA[node + 1];
    float acc = 0.f;
    for (int p = beg; p < end; p++) {
        int s = g_colA[p];
        acc += g_enc[s * 32 + lane];
    }
    int deg = end - beg;
    float val = 0.f;
    if (deg > 0) val = (acc / (float)deg) * g_sc32[lane] + g_sh32[lane];
    sAgg[node8 * 32 + lane] = val;
    __syncthreads();

    if (tid < 128) {
        int n8 = tid >> 4, d = tid & 15;
        int gn = blockIdx.x * 8 + n8;
        float a = brel[d];
        #pragma unroll
        for (int k = 0; k < 32; k++) a = fmaf(sAgg[n8 * 32 + k], sWrel[d * 32 + k], a);
        #pragma unroll
        for (int k = 0; k < 6; k++) a = fmaf(z[gn * 6 + k], Wroot[d * 7 + k], a);
        a = fmaf(land[gn], Wroot[d * 7 + 6], a);
        g_x[gn * 16 + d] = a;
        sX[tid] = a; sQ[tid] = a * a;
    }
    __syncthreads();
    #pragma unroll
    for (int off = 4; off > 0; off >>= 1) {
        if (tid < off * 16) { sX[tid] += sX[tid + off * 16]; sQ[tid] += sQ[tid + off * 16]; }
        __syncthreads();
    }
    if (tid < 16) {
        atomicAdd(&g_stats[tid], sX[tid]);
        atomicAdd(&g_stats[32 + tid], sQ[tid]);
    }
}

// ---------------- per-layer transform: BN (+ReLU) folded, compute xl, xr ----------------
__global__ __launch_bounds__(256) void k_transform(const float* __restrict__ Wl,
                                                   const float* __restrict__ bl,
                                                   const float* __restrict__ Wr,
                                                   const float* __restrict__ br,
                                                   int do_relu) {
    __shared__ float sWl[256], sWr[256], sbl[16], sbr[16], ssc[16], ssh[16];
    int tid = threadIdx.x;
    sWl[tid] = Wl[tid]; sWr[tid] = Wr[tid];
    if (tid < 16) { sbl[tid] = bl[tid]; sbr[tid] = br[tid]; ssc[tid] = g_sc16[tid]; ssh[tid] = g_sh16[tid]; }
    __syncthreads();
    int t = blockIdx.x * 256 + tid;
    int node = t >> 4, d = t & 15;
    float xb = g_x[node * 16 + d] * ssc[d] + ssh[d];
    if (do_relu) xb = fmaxf(xb, 0.f);
    float al = sbl[d], ar = sbr[d];
    #pragma unroll
    for (int k = 0; k < 16; k++) {
        float v = __shfl_sync(0xffffffffu, xb, k, 16);
        al = fmaf(sWl[d * 16 + k], v, al);
        ar = fmaf(sWr[d * 16 + k], v, ar);
    }
    g_xl[node * 16 + d] = al;
    g_xr[node * 16 + d] = ar;
}

// ---------------- GATv2: thread-per-node, no shuffles, MLP-batched edge loads ----------------
__device__ __forceinline__ void load16(float* d, const float* base, int nodeIdx) {
    const float4* p = (const float4*)(base + (size_t)nodeIdx * 16);
    #pragma unroll
    for (int q = 0; q < 4; q++) {
        float4 t = p[q];
        d[4*q] = t.x; d[4*q+1] = t.y; d[4*q+2] = t.z; d[4*q+3] = t.w;
    }
}

__device__ __forceinline__ float gat_logit(const float* xl, const float* xr, const float* at) {
    float e = 0.f;
    #pragma unroll
    for (int k = 0; k < 16; k++) {
        float u = xl[k] + xr[k];
        u = fmaxf(u, 0.f) + SLOPE * fminf(u, 0.f);
        e = fmaf(u, at[k], e);
    }
    return e;
}

__global__ __launch_bounds__(256) void k_gat(const float* __restrict__ att,
                                             const float* __restrict__ bias,
                                             int mode,                    // 0: +BN stats, 1: +pred
                                             const float* __restrict__ pW,
                                             const float* __restrict__ pb,
                                             float* __restrict__ out) {
    int tid = threadIdx.x;
    int node = blockIdx.x * 256 + tid;
    bool act = (node < N_HIGH);
    int nd = act ? node : N_HIGH - 1;

    float at[16], xr[16], x0[16], acc[16];
    #pragma unroll
    for (int k = 0; k < 16; k++) at[k] = att[k];
    load16(xr, g_xr, nd);
    load16(x0, g_xl, nd);

    // self loop
    float e0 = gat_logit(x0, xr, at);
    float w0 = __expf(e0);
    float s = w0;
    #pragma unroll
    for (int k = 0; k < 16; k++) acc[k] = w0 * x0[k];

    int beg = g_rpB[nd], end = g_rpB[nd + 1];
    int p = beg;
    for (; p + 2 <= end; p += 2) {                       // MLP: 8 LDG.128 in flight
        int s1 = g_colB[p], s2 = g_colB[p + 1];
        float x1[16], x2[16];
        load16(x1, g_xl, s1);
        load16(x2, g_xl, s2);
        float e1 = gat_logit(x1, xr, at);
        float e2 = gat_logit(x2, xr, at);
        float w1 = __expf(e1), w2 = __expf(e2);
        s += w1 + w2;
        #pragma unroll
        for (int k = 0; k < 16; k++) {
            acc[k] = fmaf(w1, x1[k], acc[k]);
            acc[k] = fmaf(w2, x2[k], acc[k]);
        }
    }
    if (p < end) {
        int s1 = g_colB[p];
        float x1[16];
        load16(x1, g_xl, s1);
        float e1 = gat_logit(x1, xr, at);
        float w1 = __expf(e1);
        s += w1;
        #pragma unroll
        for (int k = 0; k < 16; k++) acc[k] = fmaf(w1, x1[k], acc[k]);
    }

    float inv = __fdividef(1.f, s * (float)(end - beg + 1));
    float val[16];
    #pragma unroll
    for (int k = 0; k < 16; k++) val[k] = acc[k] * inv + bias[k];

    if (mode == 1) {
        float r = pb[0];
        #pragma unroll
        for (int k = 0; k < 16; k++) r = fmaf(fmaxf(val[k], 0.f), pW[k], r);
        if (act) out[node] = r;
        return;
    }

    if (act) {
        float4* dst = (float4*)(g_x + (size_t)node * 16);
        #pragma unroll
        for (int q = 0; q < 4; q++)
            dst[q] = make_float4(val[4*q], val[4*q+1], val[4*q+2], val[4*q+3]);
    }

    // BN stats: warp xor-reduce per feature, then block stage + 16 atomics
    __shared__ float sS[8][16], sQ[8][16];
    int lane = tid & 31, wrp = tid >> 5;
    #pragma unroll
    for (int k = 0; k < 16; k++) {
        float sv = act ? val[k] : 0.f;
        float qv = sv * sv;
        #pragma unroll
        for (int off = 16; off > 0; off >>= 1) {
            sv += __shfl_xor_sync(0xffffffffu, sv, off);
            qv += __shfl_xor_sync(0xffffffffu, qv, off);
        }
        if (lane == k) { sS[wrp][k] = sv; sQ[wrp][k] = qv; }
    }
    __syncthreads();
    if (tid < 16) {
        float ts = 0.f, tq = 0.f;
        #pragma unroll
        for (int w = 0; w < 8; w++) { ts += sS[w][tid]; tq += sQ[w][tid]; }
        atomicAdd(&g_stats[tid], ts);
        atomicAdd(&g_stats[32 + tid], tq);
    }
}

// ---------------- launch ----------------
extern "C" void kernel_launch(void* const* d_in, const int* in_sizes, int n_in,
                              void* d_out, int out_size) {
    const float* x_low   = (const float*)d_in[0];
    const float* z_std   = (const float*)d_in[1];
    const float* land    = (const float*)d_in[2];
    const int*   l2h_src = (const int*)d_in[3];
    const int*   l2h_dst = (const int*)d_in[4];
    const int*   hh_src  = (const int*)d_in[5];
    const int*   hh_dst  = (const int*)d_in[6];
    const float* gWih    = (const float*)d_in[7];
    const float* gWhh    = (const float*)d_in[8];
    const float* gbih    = (const float*)d_in[9];
    const float* gbhh    = (const float*)d_in[10];
    const float* dW      = (const float*)d_in[11];
    const float* db      = (const float*)d_in[12];
    const float* bnencg  = (const float*)d_in[13];
    const float* bnencb  = (const float*)d_in[14];
    const float* Wrel    = (const float*)d_in[15];
    const float* brel    = (const float*)d_in[16];
    const float* Wroot   = (const float*)d_in[17];
    const float* gWl     = (const float*)d_in[18];
    const float* gbl     = (const float*)d_in[19];
    const float* gWr     = (const float*)d_in[20];
    const float* gbr     = (const float*)d_in[21];
    const float* gatt    = (const float*)d_in[22];
    const float* gbias   = (const float*)d_in[23];
    const float* bn_g    = (const float*)d_in[24];
    const float* bn_b    = (const float*)d_in[25];
    const float* pW      = (const float*)d_in[26];
    const float* pb      = (const float*)d_in[27];
    float* out = (float*)d_out;

    k_prep<<<(N_HIGH + 255) / 256, 256>>>(gWih, gWhh, dW);             // 1 (init merged)
    k_transx<<<dim3(20, 625), dim3(32, 32)>>>(x_low);                  // 2
    k_gru<<<157, 128>>>(gbih, gbhh);                                   // 3
    k_dense4<<<313, 256>>>(db);                                        // 4  <- profiled
    k_finalize<<<1, 64>>>(bnencg, bnencb, 32, 1.f / N_LOW, 0);         // 5
    k_histAB<<<1024, 256>>>(l2h_dst, hh_dst);                          // 6
    k_scan1<<<dim3(NB_SCAN, 2), SCAN_B>>>();                           // 7
    k_scan2<<<2, 256>>>();                                             // 8
    k_scan3<<<dim3(NB_SCAN, 2), SCAN_B>>>();                           // 9
    k_fillAB<<<1024, 256>>>(l2h_src, l2h_dst, hh_src, hh_dst);         // 10
    k_aggdown<<<18750, 256>>>(z_std, land, Wrel, brel, Wroot);         // 11
    k_finalize<<<1, 64>>>(bn_g, bn_b, 16, 1.f / N_HIGH, 1);            // 12

    for (int i = 0; i < 5; i++) {
        k_transform<<<9375, 256>>>(gWl + i * 256, gbl + i * 16,
                                   gWr + i * 256, gbr + i * 16, i > 0 ? 1 : 0);
        if (i < 4) {
            k_gat<<<586, 256>>>(gatt + i * 16, gbias + i * 16, 0, nullptr, nullptr, nullptr);
            k_finalize<<<1, 64>>>(bn_g + (i + 1) * 16, bn_b + (i + 1) * 16, 16, 1.f / N_HIGH, 1);
        } else {
            k_gat<<<586, 256>>>(gatt + i * 16, gbias + i * 16, 1, pW, pb, out);
        }
    }
}